// round 13
// baseline (speedup 1.0000x reference)
#include <cuda_runtime.h>
#include <cuda_bf16.h>

// Problem constants (fixed by dataset: feats [8,64,32,32], N boxes)
#define B_    8
#define C_    64
#define H_    32
#define W_    32
#define HOUT  8
#define WOUT  8
#define MAXG  4

#define WXP   36              // WxT row pitch (floats): 144B, 16B-aligned, bank step 4
#define OYP   36              // s_tmp oy pitch (floats)
#define CLP   296             // s_tmp channel pitch (floats): 1184B, 16B-aligned

#define FMA2(d, a, b, c) asm("fma.rn.f32x2 %0, %1, %2, %3;" : "=l"(d) : "l"(a), "l"(b), "l"(c))
#define PACK2(d, lo, hi) asm("mov.b64 %0, {%1, %2};" : "=l"(d) : "f"(lo), "f"(hi))
#define UNPK2(lo, hi, s) asm("mov.b64 {%0, %1}, %2;" : "=f"(lo), "=f"(hi) : "l"(s))

// ---------------------------------------------------------------------------
// Single fused kernel: grid (N, 2); block = one box x one 32-channel half.
// Prologue: each thread ANALYTICALLY computes one Wy entry and one Wx entry
// (gather form of the reference's sample scatter) -> no atomics, ONE barrier.
// Ranges (ballots) are computed per-warp after the barrier (no 2nd barrier).
//   out[oy][ox][c] = sum_y sum_x Wy[y][oy] * Wx[x][ox] * f[c][y][x]
// ---------------------------------------------------------------------------
__global__ __launch_bounds__(256, 4)
void roi_kernel(const float* __restrict__ feats,
                const int* __restrict__ batch_idxs,
                const int* __restrict__ starts,
                const int* __restrict__ goals,
                float* __restrict__ out) {
    const int n   = blockIdx.x;
    const int h   = blockIdx.y;
    const int tid = threadIdx.x;

    __shared__ unsigned long long s_Wy2[H_ * 8];   // packed {w,w}, [y][oy]
    __shared__ float s_WxT[8 * WXP];               // [ox][x]
    __shared__ float s_tmp[32 * CLP];              // [cl][oy][x]

    // --- per-box geometry (every thread; broadcast loads) ---
    const float sy = (float)__ldg(&starts[2 * n + 0]);
    const float sx = (float)__ldg(&starts[2 * n + 1]);
    const float gy = (float)__ldg(&goals[2 * n + 0]);
    const float gx = (float)__ldg(&goals[2 * n + 1]);
    const int   b  = __ldg(&batch_idxs[n]);
    const int  cse = ((sy > gy) ? 2 : 0) + ((sx > gx) ? 1 : 0);

    const float y_min = fminf(sy, gy), y_max = fmaxf(sy, gy);
    const float x_min = fminf(sx, gx), x_max = fmaxf(sx, gx);
    const float start_h = y_min - 0.5f;
    const float start_w = x_min - 0.5f;
    const float bin_h = (y_max - y_min) / (float)HOUT;
    const float bin_w = (x_max - x_min) / (float)WOUT;
    const int gh = (int)ceilf(bin_h);
    const int gw = (int)ceilf(bin_w);
    const float invc = 1.0f / (float)max(gh * gw, 1);

    // --- Wy entry (gather form): y = tid>>3, oy = tid&7 ---
    {
        const int   yq  = tid >> 3;
        const float phf = (float)(tid & 7);
        const float gsafe = fmaxf((float)gh, 1.0f);
        const float step  = bin_h / gsafe;
        const float base  = start_h + phf * bin_h;
        float wy = 0.0f;
        #pragma unroll
        for (int i = 0; i < MAXG; i++) {
            const float pos = base + ((float)i + 0.5f) * step;
            const bool  valid = (pos >= -1.0f) && (pos <= 32.0f) && (i < gh);
            const float p     = fminf(fmaxf(pos, 0.0f), 31.0f);
            const float lowf  = floorf(p);
            const int   low   = (int)lowf;
            const int   high  = min(low + 1, H_ - 1);
            const float l     = p - lowf;
            const float vf    = valid ? 1.0f : 0.0f;
            if (low  == yq) wy += (1.0f - l) * vf;
            if (high == yq) wy += l * vf;
        }
        wy *= invc;
        unsigned long long pw;
        PACK2(pw, wy, wy);
        s_Wy2[tid] = pw;
    }

    // --- Wx entry (gather form): ox = tid>>5, x = tid&31 ---
    {
        const int   xq  = tid & 31;
        const float phf = (float)(tid >> 5);
        const float gsafe = fmaxf((float)gw, 1.0f);
        const float step  = bin_w / gsafe;
        const float base  = start_w + phf * bin_w;
        float wx = 0.0f;
        #pragma unroll
        for (int i = 0; i < MAXG; i++) {
            const float pos = base + ((float)i + 0.5f) * step;
            const bool  valid = (pos >= -1.0f) && (pos <= 32.0f) && (i < gw);
            const float p     = fminf(fmaxf(pos, 0.0f), 31.0f);
            const float lowf  = floorf(p);
            const int   low   = (int)lowf;
            const int   high  = min(low + 1, W_ - 1);
            const float l     = p - lowf;
            const float vf    = valid ? 1.0f : 0.0f;
            if (low  == xq) wx += (1.0f - l) * vf;
            if (high == xq) wx += l * vf;
        }
        s_WxT[(tid >> 5) * WXP + (tid & 31)] = wx;
    }
    // zero WxT padding columns 32..35 (read with zero weight by pass B)
    if (tid < 32) s_WxT[(tid & 7) * WXP + 32 + (tid >> 3)] = 0.0f;

    __syncthreads();   // the only block-wide barrier

    const int warp = tid >> 5;
    const int lane = tid & 31;

    // --- per-warp range detection (reads smem written before the barrier) ---
    int ylA0, ylB0, cn0, ylA1, ylB1, cn1, xc0, ncx;
    {
        int ylo[4], cnt[4];
        #pragma unroll
        for (int pp = 0; pp < 4; pp++) {
            const bool nz = (s_Wy2[lane * 8 + 2 * pp]     != 0ull) ||
                            (s_Wy2[lane * 8 + 2 * pp + 1] != 0ull);
            unsigned m = __ballot_sync(0xffffffffu, nz);
            ylo[pp] = m ? (__ffs(m) - 1) : 0;
            cnt[pp] = m ? (32 - __clz(m)) - ylo[pp] : 0;
        }
        cn0  = max(cnt[0], cnt[1]);
        cn1  = max(cnt[2], cnt[3]);
        ylA0 = min(ylo[0], H_ - cn0);
        ylB0 = min(ylo[1], H_ - cn0);
        ylA1 = min(ylo[2], H_ - cn1);
        ylB1 = min(ylo[3], H_ - cn1);

        float s = 0.0f;
        #pragma unroll
        for (int ox = 0; ox < 8; ox++) s += s_WxT[ox * WXP + lane];
        unsigned m = __ballot_sync(0xffffffffu, s != 0.0f);
        if (m) {
            const int x0 = __ffs(m) - 1;
            const int x1 = 32 - __clz(m);            // exclusive
            xc0 = x0 & ~3;
            ncx = (x1 - xc0 + 3) >> 2;
        } else { xc0 = 0; ncx = 0; }
    }

    // ---- Pass A: tmp[cl][oy][x] = sum_y Wy[y][oy] * f[c][y][x] ----
    // Two loops; each interleaves 2 bin-pairs (2 independent LDG.128/iter).
    {
        const int cc = lane >> 3;             // channel within warp (0..3)
        const int xg = lane & 7;              // x group (4 floats)
        const int cl = warp * 4 + cc;
        const int c  = h * 32 + cl;

        const ulonglong2* __restrict__ fp = (const ulonglong2*)
            (feats + (size_t)(b * C_ + c) * (H_ * W_)) + xg;
        float* tp = s_tmp + cl * CLP + 4 * xg;

        #pragma unroll
        for (int g = 0; g < 2; g++) {
            const int ylA = g ? ylA1 : ylA0;
            const int ylB = g ? ylB1 : ylB0;
            const int cn  = g ? cn1  : cn0;

            const ulonglong2* fqA = fp + (size_t)ylA * 8;
            const ulonglong2* fqB = fp + (size_t)ylB * 8;

            unsigned long long acc[8];
            #pragma unroll
            for (int k = 0; k < 8; k++) acc[k] = 0ull;

            #pragma unroll 2
            for (int t = 0; t < cn; t++) {
                const ulonglong2 vA = __ldg(fqA + (size_t)t * 8);
                const ulonglong2 vB = __ldg(fqB + (size_t)t * 8);
                const ulonglong2 wA =
                    *(const ulonglong2*)&s_Wy2[(ylA + t) * 8 + 4 * g];      // bins 4g,4g+1
                const ulonglong2 wB =
                    *(const ulonglong2*)&s_Wy2[(ylB + t) * 8 + 4 * g + 2];  // bins 4g+2,4g+3
                FMA2(acc[0], vA.x, wA.x, acc[0]); FMA2(acc[1], vA.y, wA.x, acc[1]);
                FMA2(acc[2], vA.x, wA.y, acc[2]); FMA2(acc[3], vA.y, wA.y, acc[3]);
                FMA2(acc[4], vB.x, wB.x, acc[4]); FMA2(acc[5], vB.y, wB.x, acc[5]);
                FMA2(acc[6], vB.x, wB.y, acc[6]); FMA2(acc[7], vB.y, wB.y, acc[7]);
            }

            #pragma unroll
            for (int k = 0; k < 4; k++) {
                ulonglong2 r;
                r.x = acc[2 * k];
                r.y = acc[2 * k + 1];
                *reinterpret_cast<ulonglong2*>(tp + (4 * g + k) * OYP) = r;
            }
        }
        // zero s_tmp padding x=32..35 for this warp's 4 channels x 8 oy
        // (read with zero weight by pass B; must be finite)
        {
            const int zch = lane >> 3;        // 0..3
            const int zoy = lane & 7;         // 0..7
            float4 z; z.x = 0.f; z.y = 0.f; z.z = 0.f; z.w = 0.f;
            *reinterpret_cast<float4*>(
                s_tmp + (warp * 4 + zch) * CLP + zoy * OYP + 32) = z;
        }
    }
    __syncwarp();      // warp-local: pass B reads only this warp's tmp region

    // ---- Pass B: out[c][bin] = sum_x Wx[x][ox_s] * tmp[cl][oy_s][x] ----
    {
        #pragma unroll
        for (int half = 0; half < 2; half++) {
            const int bin = half * 32 + lane;
            const int py  = bin >> 3;
            const int px  = bin & 7;
            int oy_s, ox_s;                    // source bin after flip
            if      (cse == 0) { oy_s = py;     ox_s = px;     }
            else if (cse == 3) { oy_s = 7 - py; ox_s = px;     }
            else               { oy_s = py;     ox_s = 7 - py; }

            unsigned long long a2[4];
            #pragma unroll
            for (int ch = 0; ch < 4; ch++) a2[ch] = 0ull;

            const float* wrow = s_WxT + ox_s * WXP;
            const float* trow = s_tmp + (warp * 4) * CLP + oy_s * OYP;

            for (int k = 0; k < ncx; k++) {
                const int x4 = xc0 + 4 * k;
                const ulonglong2 wv = *reinterpret_cast<const ulonglong2*>(wrow + x4);
                #pragma unroll
                for (int ch = 0; ch < 4; ch++) {
                    const ulonglong2 tv =
                        *reinterpret_cast<const ulonglong2*>(trow + ch * CLP + x4);
                    FMA2(a2[ch], tv.x, wv.x, a2[ch]);
                    FMA2(a2[ch], tv.y, wv.y, a2[ch]);
                }
            }

            float* __restrict__ ob =
                out + (size_t)n * (C_ * HOUT * WOUT)
                    + (size_t)(h * 32 + warp * 4) * 64 + bin;
            #pragma unroll
            for (int ch = 0; ch < 4; ch++) {
                float lo, hi;
                UNPK2(lo, hi, a2[ch]);
                ob[(size_t)ch * 64] = lo + hi;     // 128B coalesced per (half,ch)
            }
        }
    }
}

extern "C" void kernel_launch(void* const* d_in, const int* in_sizes, int n_in,
                              void* d_out, int out_size) {
    const float* feats      = (const float*)d_in[0];
    const int*   batch_idxs = (const int*)d_in[1];
    const int*   starts     = (const int*)d_in[2];
    const int*   goals      = (const int*)d_in[3];
    float*       out        = (float*)d_out;

    const int N = in_sizes[1];   // number of boxes (1024)

    dim3 grid(N, 2);
    roi_kernel<<<grid, 256>>>(feats, batch_idxs, starts, goals, out);
}

// round 14
// speedup vs baseline: 1.0808x; 1.0808x over previous
#include <cuda_runtime.h>
#include <cuda_bf16.h>

// Problem constants (fixed by dataset: feats [8,64,32,32], N boxes)
#define B_    8
#define C_    64
#define H_    32
#define W_    32
#define HOUT  8
#define WOUT  8

#define WXP   36              // WxT row pitch (floats): 144B, 16B-aligned, bank step 4
#define OYP   36              // s_tmp oy pitch (floats)
#define CLP   296             // s_tmp channel pitch (floats): 1184B, 16B-aligned

#define NMAX  4096

#define FMA2(d, a, b, c) asm("fma.rn.f32x2 %0, %1, %2, %3;" : "=l"(d) : "l"(a), "l"(b), "l"(c))
#define PACK2(d, lo, hi) asm("mov.b64 %0, {%1, %2};" : "=l"(d) : "f"(lo), "f"(hi))
#define UNPK2(lo, hi, s) asm("mov.b64 {%0, %1}, %2;" : "=f"(lo), "=f"(hi) : "l"(s))

// Per-box precomputed weights (prep kernel -> main kernel)
__device__ unsigned long long g_Wy2[NMAX * 256];      // [n][y*8+oy], packed {w,w}
__device__ float              g_WxT[NMAX * 8 * WXP];  // [n][ox][x]
__device__ int                g_hdr[NMAX * 8];        // xc0,ncx,case,b,ylo_pack,cnt_pack

// ---------------------------------------------------------------------------
// Prep kernel: 4 boxes per 256-thread block; 64 threads per box.
// Computes sampling weight matrices + per-bin-pair active y-ranges.
// ---------------------------------------------------------------------------
__global__ void prep_kernel(const int* __restrict__ batch_idxs,
                            const int* __restrict__ starts,
                            const int* __restrict__ goals, int N) {
    const int tid = threadIdx.x;
    const int bl  = tid >> 6;
    const int sub = tid & 63;
    const int n   = blockIdx.x * 4 + bl;

    __shared__ float s_Wy[4][H_ * 8];
    __shared__ float s_Wx[4][8 * WXP];

    for (int k = sub; k < H_ * 8;  k += 64) s_Wy[bl][k] = 0.0f;
    for (int k = sub; k < 8 * WXP; k += 64) s_Wx[bl][k] = 0.0f;
    __syncthreads();

    if (n < N) {
        const float sy = (float)starts[2 * n + 0];
        const float sx = (float)starts[2 * n + 1];
        const float gy = (float)goals[2 * n + 0];
        const float gx = (float)goals[2 * n + 1];
        const float y_min = fminf(sy, gy), y_max = fmaxf(sy, gy);
        const float x_min = fminf(sx, gx), x_max = fmaxf(sx, gx);

        const float start_h = y_min - 0.5f;
        const float start_w = x_min - 0.5f;
        const float bin_h = (y_max - y_min) / (float)HOUT;
        const float bin_w = (x_max - x_min) / (float)WOUT;
        const int gh = (int)ceilf(bin_h);
        const int gw = (int)ceilf(bin_w);
        const float invc = 1.0f / (float)max(gh * gw, 1);

        const int axis = sub >> 5;            // 0 = y, 1 = x
        const int idx  = sub & 31;
        const int ph   = idx >> 2;
        const int i    = idx & 3;

        const float start  = axis ? start_w : start_h;
        const float bin_sz = axis ? bin_w  : bin_h;
        const int   grid   = axis ? gw     : gh;
        const float size   = 32.0f;

        const float g_safe = fmaxf((float)grid, 1.0f);
        const float pos    = start + (float)ph * bin_sz
                           + ((float)i + 0.5f) * (bin_sz / g_safe);
        const bool  valid  = (pos >= -1.0f) && (pos <= size) && (i < grid);
        const float p      = fminf(fmaxf(pos, 0.0f), size - 1.0f);
        const float lowf   = floorf(p);
        const int   low    = (int)lowf;
        const int   high   = min(low + 1, (int)size - 1);
        const float l      = p - lowf;
        const float vf     = valid ? 1.0f : 0.0f;

        if (axis == 0) {
            atomicAdd(&s_Wy[bl][low  * 8 + ph], (1.0f - l) * vf * invc);
            atomicAdd(&s_Wy[bl][high * 8 + ph], l * vf * invc);
        } else {
            atomicAdd(&s_Wx[bl][ph * WXP + low ], (1.0f - l) * vf);
            atomicAdd(&s_Wx[bl][ph * WXP + high], l * vf);
        }

        if (sub == 0) {
            g_hdr[n * 8 + 2] = ((sy > gy) ? 2 : 0) + ((sx > gx) ? 1 : 0);
            g_hdr[n * 8 + 3] = batch_idxs[n];
        }
    }
    __syncthreads();

    if (n < N) {
        if (sub < 32) {
            // per-bin-pair active y ranges: pairs (0,1),(2,3),(4,5),(6,7)
            const int yr = sub;               // lane = y row
            unsigned ylo_pack = 0, cnt_pack = 0;
            #pragma unroll
            for (int pp = 0; pp < 4; pp++) {
                const bool nz = (s_Wy[bl][yr * 8 + 2 * pp]     != 0.0f) ||
                                (s_Wy[bl][yr * 8 + 2 * pp + 1] != 0.0f);
                unsigned m = __ballot_sync(0xffffffffu, nz);
                int ylo = 0, cnt = 0;
                if (m) {
                    ylo = __ffs(m) - 1;
                    cnt = (32 - __clz(m)) - ylo;
                    cnt = (cnt + 1) & ~1;          // pad to even (pad rows have w==0)
                    ylo = min(ylo, H_ - cnt);      // keep in bounds
                }
                ylo_pack |= (unsigned)ylo << (pp * 8);
                cnt_pack |= (unsigned)cnt << (pp * 8);
            }
            if (sub == 0) {
                g_hdr[n * 8 + 4] = (int)ylo_pack;
                g_hdr[n * 8 + 5] = (int)cnt_pack;
            }
        } else {
            const int lane = sub - 32;
            float s = 0.0f;
            #pragma unroll
            for (int ox = 0; ox < 8; ox++) s += s_Wx[bl][ox * WXP + lane];
            unsigned m = __ballot_sync(0xffffffffu, s != 0.0f);
            if (lane == 0) {
                if (m) {
                    const int x0  = __ffs(m) - 1;
                    const int x1  = 32 - __clz(m);          // exclusive
                    const int xc0 = x0 & ~3;
                    g_hdr[n * 8 + 0] = xc0;
                    g_hdr[n * 8 + 1] = (x1 - xc0 + 3) >> 2;
                } else { g_hdr[n * 8 + 0] = 0; g_hdr[n * 8 + 1] = 0; }
            }
        }
        for (int k = sub; k < H_ * 8; k += 64) {
            const float w = s_Wy[bl][k];
            unsigned long long pw;
            PACK2(pw, w, w);
            g_Wy2[n * 256 + k] = pw;
        }
        for (int k = sub; k < 8 * WXP; k += 64)
            g_WxT[n * 8 * WXP + k] = s_Wx[bl][k];
    }
}

// ---------------------------------------------------------------------------
// Main kernel: grid (N, 2). One weight-copy + single block barrier, then
// warp-independent passes. Pass A iterates per-bin-pair over only the rows
// with nonzero weights. Pass B has a broadcast fast path for flip cases 1/2
// (output row = single bin value), ~6x less pass-B work for those boxes.
// ---------------------------------------------------------------------------
__global__ __launch_bounds__(256, 5)
void roi_kernel(const float* __restrict__ feats, float* __restrict__ out) {
    const int n   = blockIdx.x;
    const int h   = blockIdx.y;
    const int tid = threadIdx.x;

    __shared__ unsigned long long s_Wy2[H_ * 8];   // packed {w,w}
    __shared__ float s_WxT[8 * WXP];               // [ox][x]
    __shared__ float s_tmp[32 * CLP];              // [cl][oy][x]

#if __CUDA_ARCH__ >= 900
    cudaGridDependencySynchronize();               // PDL: wait for prep results
#endif

    // coalesced weight copy
    s_Wy2[tid] = g_Wy2[n * 256 + tid];
    if (tid < 8 * WXP)        s_WxT[tid]       = g_WxT[n * 8 * WXP + tid];
    if (tid < 8 * WXP - 256)  s_WxT[256 + tid] = g_WxT[n * 8 * WXP + 256 + tid];

    const int xc0  = __ldg(&g_hdr[n * 8 + 0]);
    const int ncx  = __ldg(&g_hdr[n * 8 + 1]);
    const int cse  = __ldg(&g_hdr[n * 8 + 2]);
    const int b    = __ldg(&g_hdr[n * 8 + 3]);
    const unsigned ylop = (unsigned)__ldg(&g_hdr[n * 8 + 4]);
    const unsigned cntp = (unsigned)__ldg(&g_hdr[n * 8 + 5]);
    __syncthreads();   // the only block-wide barrier

    const int warp = tid >> 5;
    const int lane = tid & 31;

    // ---- Pass A: tmp[cl][oy][x] = sum_y Wy[y][oy] * f[c][y][x] ----
    // Per bin-pair, iterate only rows with nonzero weights (count is even).
    {
        const int cc = lane >> 3;             // channel within warp (0..3)
        const int xg = lane & 7;              // x group (4 floats)
        const int cl = warp * 4 + cc;
        const int c  = h * 32 + cl;

        const ulonglong2* __restrict__ fp = (const ulonglong2*)
            (feats + (size_t)(b * C_ + c) * (H_ * W_)) + xg;
        float* tp = s_tmp + cl * CLP + 4 * xg;

        #pragma unroll
        for (int pp = 0; pp < 4; pp++) {
            const int yl = (int)((ylop >> (pp * 8)) & 0xFF);
            const int cn = (int)((cntp >> (pp * 8)) & 0xFF);   // even

            unsigned long long a00 = 0ull, a01 = 0ull, a10 = 0ull, a11 = 0ull;
            const ulonglong2* fq = fp + (size_t)yl * 8;
            const ulonglong2* wq = (const ulonglong2*)&s_Wy2[yl * 8 + 2 * pp];

            for (int t = 0; t < cn; t += 2) {
                const ulonglong2 v0 = __ldg(fq + (size_t)t * 8);
                const ulonglong2 v1 = __ldg(fq + (size_t)t * 8 + 8);
                const ulonglong2 w0 = wq[t * 4];        // {w(2pp), w(2pp+1)} row t
                const ulonglong2 w1 = wq[t * 4 + 4];    // row t+1
                FMA2(a00, v0.x, w0.x, a00); FMA2(a01, v0.y, w0.x, a01);
                FMA2(a10, v0.x, w0.y, a10); FMA2(a11, v0.y, w0.y, a11);
                FMA2(a00, v1.x, w1.x, a00); FMA2(a01, v1.y, w1.x, a01);
                FMA2(a10, v1.x, w1.y, a10); FMA2(a11, v1.y, w1.y, a11);
            }

            ulonglong2 r0; r0.x = a00; r0.y = a01;
            ulonglong2 r1; r1.x = a10; r1.y = a11;
            *reinterpret_cast<ulonglong2*>(tp + (2 * pp) * OYP)     = r0;
            *reinterpret_cast<ulonglong2*>(tp + (2 * pp + 1) * OYP) = r1;
        }
    }
    __syncwarp();      // warp-local: pass B reads only this warp's tmp region

    // ---- Pass B: out[c][bin] = sum_x Wx[x][ox_s] * tmp[cl][oy_s][x] ----
    if (cse == 1 || cse == 2) {
        // Broadcast fast path: flip table maps every px of row py to source
        // bin (py, 7-py) -> one reduction per (ch,py), row written 8x.
        const int cc = lane >> 3;             // channel within warp (0..3)
        const int py = lane & 7;
        const int oxs = 7 - py;

        unsigned long long a2 = 0ull;
        const float* wrow = s_WxT + oxs * WXP;
        const float* trow = s_tmp + (warp * 4 + cc) * CLP + py * OYP;

        for (int k = 0; k < ncx; k++) {
            const int x4 = xc0 + 4 * k;
            const ulonglong2 wv = *reinterpret_cast<const ulonglong2*>(wrow + x4);
            const ulonglong2 tv = *reinterpret_cast<const ulonglong2*>(trow + x4);
            FMA2(a2, tv.x, wv.x, a2);
            FMA2(a2, tv.y, wv.y, a2);
        }
        float lo, hi;
        UNPK2(lo, hi, a2);
        const float v = lo + hi;
        float4 q; q.x = v; q.y = v; q.z = v; q.w = v;

        float* __restrict__ ob =
            out + (size_t)n * (C_ * HOUT * WOUT)
                + (size_t)(h * 32 + warp * 4 + cc) * 64 + py * 8;
        *reinterpret_cast<float4*>(ob)     = q;
        *reinterpret_cast<float4*>(ob + 4) = q;
    } else {
        // General path (cse 0 or 3): per-bin reduction.
        #pragma unroll
        for (int half = 0; half < 2; half++) {
            const int bin = half * 32 + lane;
            const int py  = bin >> 3;
            const int px  = bin & 7;
            const int oy_s = (cse == 0) ? py : 7 - py;
            const int ox_s = px;

            unsigned long long a2[4];
            #pragma unroll
            for (int ch = 0; ch < 4; ch++) a2[ch] = 0ull;

            const float* wrow = s_WxT + ox_s * WXP;
            const float* trow = s_tmp + (warp * 4) * CLP + oy_s * OYP;

            for (int k = 0; k < ncx; k++) {
                const int x4 = xc0 + 4 * k;
                const ulonglong2 wv = *reinterpret_cast<const ulonglong2*>(wrow + x4);
                #pragma unroll
                for (int ch = 0; ch < 4; ch++) {
                    const ulonglong2 tv =
                        *reinterpret_cast<const ulonglong2*>(trow + ch * CLP + x4);
                    FMA2(a2[ch], tv.x, wv.x, a2[ch]);
                    FMA2(a2[ch], tv.y, wv.y, a2[ch]);
                }
            }

            float* __restrict__ ob =
                out + (size_t)n * (C_ * HOUT * WOUT)
                    + (size_t)(h * 32 + warp * 4) * 64 + bin;
            #pragma unroll
            for (int ch = 0; ch < 4; ch++) {
                float lo, hi;
                UNPK2(lo, hi, a2[ch]);
                ob[(size_t)ch * 64] = lo + hi;     // 128B coalesced per (half,ch)
            }
        }
    }
}

extern "C" void kernel_launch(void* const* d_in, const int* in_sizes, int n_in,
                              void* d_out, int out_size) {
    const float* feats      = (const float*)d_in[0];
    const int*   batch_idxs = (const int*)d_in[1];
    const int*   starts     = (const int*)d_in[2];
    const int*   goals      = (const int*)d_in[3];
    float*       out        = (float*)d_out;

    const int N = in_sizes[1];   // number of boxes (1024)

    prep_kernel<<<(N + 3) / 4, 256>>>(batch_idxs, starts, goals, N);

    // roi kernel launched with PDL so its blocks spin up while prep drains;
    // cudaGridDependencySynchronize() in-kernel guards the data dependency.
    cudaLaunchConfig_t cfg = {};
    cfg.gridDim  = dim3((unsigned)N, 2, 1);
    cfg.blockDim = dim3(256, 1, 1);
    cfg.dynamicSmemBytes = 0;
    cudaLaunchAttribute attr[1];
    attr[0].id = cudaLaunchAttributeProgrammaticStreamSerialization;
    attr[0].val.programmaticStreamSerializationAllowed = 1;
    cfg.attrs = attr;
    cfg.numAttrs = 1;
    cudaLaunchKernelEx(&cfg, roi_kernel, feats, out);
}

// round 15
// speedup vs baseline: 1.1889x; 1.1000x over previous
#include <cuda_runtime.h>
#include <cuda_bf16.h>

// Problem constants (fixed by dataset: feats [8,64,32,32], N boxes)
#define B_    8
#define C_    64
#define H_    32
#define W_    32
#define HOUT  8
#define WOUT  8

#define WXP   36              // WxT row pitch (floats): 144B, 16B-aligned, bank step 4
#define OYP   36              // s_tmp oy pitch (floats)
#define CLP   296             // s_tmp channel pitch (floats): 1184B, 16B-aligned

#define NMAX  4096

#define FMA2(d, a, b, c) asm("fma.rn.f32x2 %0, %1, %2, %3;" : "=l"(d) : "l"(a), "l"(b), "l"(c))
#define PACK2(d, lo, hi) asm("mov.b64 %0, {%1, %2};" : "=l"(d) : "f"(lo), "f"(hi))
#define UNPK2(lo, hi, s) asm("mov.b64 {%0, %1}, %2;" : "=f"(lo), "=f"(hi) : "l"(s))

// Per-box precomputed weights (prep kernel -> main kernel)
__device__ unsigned long long g_Wy2[NMAX * 256];      // [n][y*8+oy], packed {w,w}
__device__ float              g_WxT[NMAX * 8 * WXP];  // [n][ox][x]
__device__ int                g_hdr[NMAX * 8];        // xc0,ncx,case,b,ylo_pack,cnt_pack

// ---------------------------------------------------------------------------
// Prep kernel: 4 boxes per 256-thread block; 64 threads per box.
// Computes weight matrices + per-bin-pair y-starts, with pair-GROUP row counts
// (group 0 = pairs {0,1}, group 1 = pairs {2,3}; count = max within group).
// ---------------------------------------------------------------------------
__global__ void prep_kernel(const int* __restrict__ batch_idxs,
                            const int* __restrict__ starts,
                            const int* __restrict__ goals, int N) {
    const int tid = threadIdx.x;
    const int bl  = tid >> 6;
    const int sub = tid & 63;
    const int n   = blockIdx.x * 4 + bl;

    __shared__ float s_Wy[4][H_ * 8];
    __shared__ float s_Wx[4][8 * WXP];

    for (int k = sub; k < H_ * 8;  k += 64) s_Wy[bl][k] = 0.0f;
    for (int k = sub; k < 8 * WXP; k += 64) s_Wx[bl][k] = 0.0f;
    __syncthreads();

    if (n < N) {
        const float sy = (float)starts[2 * n + 0];
        const float sx = (float)starts[2 * n + 1];
        const float gy = (float)goals[2 * n + 0];
        const float gx = (float)goals[2 * n + 1];
        const float y_min = fminf(sy, gy), y_max = fmaxf(sy, gy);
        const float x_min = fminf(sx, gx), x_max = fmaxf(sx, gx);

        const float start_h = y_min - 0.5f;
        const float start_w = x_min - 0.5f;
        const float bin_h = (y_max - y_min) / (float)HOUT;
        const float bin_w = (x_max - x_min) / (float)WOUT;
        const int gh = (int)ceilf(bin_h);
        const int gw = (int)ceilf(bin_w);
        const float invc = 1.0f / (float)max(gh * gw, 1);

        const int axis = sub >> 5;            // 0 = y, 1 = x
        const int idx  = sub & 31;
        const int ph   = idx >> 2;
        const int i    = idx & 3;

        const float start  = axis ? start_w : start_h;
        const float bin_sz = axis ? bin_w  : bin_h;
        const int   grid   = axis ? gw     : gh;
        const float size   = 32.0f;

        const float g_safe = fmaxf((float)grid, 1.0f);
        const float pos    = start + (float)ph * bin_sz
                           + ((float)i + 0.5f) * (bin_sz / g_safe);
        const bool  valid  = (pos >= -1.0f) && (pos <= size) && (i < grid);
        const float p      = fminf(fmaxf(pos, 0.0f), size - 1.0f);
        const float lowf   = floorf(p);
        const int   low    = (int)lowf;
        const int   high   = min(low + 1, (int)size - 1);
        const float l      = p - lowf;
        const float vf     = valid ? 1.0f : 0.0f;

        if (axis == 0) {
            atomicAdd(&s_Wy[bl][low  * 8 + ph], (1.0f - l) * vf * invc);
            atomicAdd(&s_Wy[bl][high * 8 + ph], l * vf * invc);
        } else {
            atomicAdd(&s_Wx[bl][ph * WXP + low ], (1.0f - l) * vf);
            atomicAdd(&s_Wx[bl][ph * WXP + high], l * vf);
        }

        if (sub == 0) {
            g_hdr[n * 8 + 2] = ((sy > gy) ? 2 : 0) + ((sx > gx) ? 1 : 0);
            g_hdr[n * 8 + 3] = batch_idxs[n];
        }
    }
    __syncthreads();

    if (n < N) {
        if (sub < 32) {
            // per-bin-pair y starts + per-GROUP shared row counts
            const int yr = sub;               // lane = y row
            int ylo[4], cnt[4];
            #pragma unroll
            for (int pp = 0; pp < 4; pp++) {
                const bool nz = (s_Wy[bl][yr * 8 + 2 * pp]     != 0.0f) ||
                                (s_Wy[bl][yr * 8 + 2 * pp + 1] != 0.0f);
                unsigned m = __ballot_sync(0xffffffffu, nz);
                ylo[pp] = m ? (__ffs(m) - 1) : 0;
                cnt[pp] = m ? (32 - __clz(m)) - ylo[pp] : 0;
            }
            if (sub == 0) {
                const int cn0 = max(max(cnt[0], cnt[1]), 1);
                const int cn1 = max(max(cnt[2], cnt[3]), 1);
                unsigned ylop = 0;
                ylop |= (unsigned)min(ylo[0], H_ - cn0);
                ylop |= (unsigned)min(ylo[1], H_ - cn0) << 8;
                ylop |= (unsigned)min(ylo[2], H_ - cn1) << 16;
                ylop |= (unsigned)min(ylo[3], H_ - cn1) << 24;
                g_hdr[n * 8 + 4] = (int)ylop;
                g_hdr[n * 8 + 5] = cn0 | (cn1 << 8);
            }
        } else {
            const int lane = sub - 32;
            float s = 0.0f;
            #pragma unroll
            for (int ox = 0; ox < 8; ox++) s += s_Wx[bl][ox * WXP + lane];
            unsigned m = __ballot_sync(0xffffffffu, s != 0.0f);
            if (lane == 0) {
                if (m) {
                    const int x0  = __ffs(m) - 1;
                    const int x1  = 32 - __clz(m);          // exclusive
                    const int xc0 = x0 & ~3;
                    g_hdr[n * 8 + 0] = xc0;
                    g_hdr[n * 8 + 1] = (x1 - xc0 + 3) >> 2;
                } else { g_hdr[n * 8 + 0] = 0; g_hdr[n * 8 + 1] = 0; }
            }
        }
        for (int k = sub; k < H_ * 8; k += 64) {
            const float w = s_Wy[bl][k];
            unsigned long long pw;
            PACK2(pw, w, w);
            g_Wy2[n * 256 + k] = pw;
        }
        for (int k = sub; k < 8 * WXP; k += 64)
            g_WxT[n * 8 * WXP + k] = s_Wx[bl][k];
    }
}

// ---------------------------------------------------------------------------
// Main kernel: grid (N, 2). Weight copy + single barrier, then warp-private
// passes. Pass A: two loops, each interleaving 2 bin-pairs (2 independent
// LDG.128/iter, unroll 2 -> ~4 loads in flight; acc = 16 regs per loop).
// Pass B keeps the broadcast fast path for flip cases 1/2.
// ---------------------------------------------------------------------------
__global__ __launch_bounds__(256, 4)
void roi_kernel(const float* __restrict__ feats, float* __restrict__ out) {
    const int n   = blockIdx.x;
    const int h   = blockIdx.y;
    const int tid = threadIdx.x;

    __shared__ unsigned long long s_Wy2[H_ * 8];   // packed {w,w}
    __shared__ float s_WxT[8 * WXP];               // [ox][x]
    __shared__ float s_tmp[32 * CLP];              // [cl][oy][x]

#if __CUDA_ARCH__ >= 900
    cudaGridDependencySynchronize();               // PDL: wait for prep results
#endif

    // coalesced weight copy
    s_Wy2[tid] = g_Wy2[n * 256 + tid];
    if (tid < 8 * WXP)        s_WxT[tid]       = g_WxT[n * 8 * WXP + tid];
    if (tid < 8 * WXP - 256)  s_WxT[256 + tid] = g_WxT[n * 8 * WXP + 256 + tid];

    const int xc0  = __ldg(&g_hdr[n * 8 + 0]);
    const int ncx  = __ldg(&g_hdr[n * 8 + 1]);
    const int cse  = __ldg(&g_hdr[n * 8 + 2]);
    const int b    = __ldg(&g_hdr[n * 8 + 3]);
    const unsigned ylop = (unsigned)__ldg(&g_hdr[n * 8 + 4]);
    const int      cntp = __ldg(&g_hdr[n * 8 + 5]);
    __syncthreads();   // the only block-wide barrier

    const int warp = tid >> 5;
    const int lane = tid & 31;

    // ---- Pass A: tmp[cl][oy][x] = sum_y Wy[y][oy] * f[c][y][x] ----
    // Two loops; each interleaves 2 bin-pairs (2 independent LDG.128/iter).
    {
        const int cc = lane >> 3;             // channel within warp (0..3)
        const int xg = lane & 7;              // x group (4 floats)
        const int cl = warp * 4 + cc;
        const int c  = h * 32 + cl;

        const ulonglong2* __restrict__ fp = (const ulonglong2*)
            (feats + (size_t)(b * C_ + c) * (H_ * W_)) + xg;
        float* tp = s_tmp + cl * CLP + 4 * xg;

        #pragma unroll
        for (int g = 0; g < 2; g++) {
            const int ylA = (int)((ylop >> (g * 16))     & 0xFF);
            const int ylB = (int)((ylop >> (g * 16 + 8)) & 0xFF);
            const int cn  = (cntp >> (g * 8)) & 0xFF;

            const ulonglong2* fqA = fp + (size_t)ylA * 8;
            const ulonglong2* fqB = fp + (size_t)ylB * 8;

            unsigned long long acc[8];
            #pragma unroll
            for (int k = 0; k < 8; k++) acc[k] = 0ull;

            #pragma unroll 2
            for (int t = 0; t < cn; t++) {
                const ulonglong2 vA = __ldg(fqA + (size_t)t * 8);
                const ulonglong2 vB = __ldg(fqB + (size_t)t * 8);
                const ulonglong2 wA =
                    *(const ulonglong2*)&s_Wy2[(ylA + t) * 8 + 4 * g];      // bins 4g,4g+1
                const ulonglong2 wB =
                    *(const ulonglong2*)&s_Wy2[(ylB + t) * 8 + 4 * g + 2];  // bins 4g+2,4g+3
                FMA2(acc[0], vA.x, wA.x, acc[0]); FMA2(acc[1], vA.y, wA.x, acc[1]);
                FMA2(acc[2], vA.x, wA.y, acc[2]); FMA2(acc[3], vA.y, wA.y, acc[3]);
                FMA2(acc[4], vB.x, wB.x, acc[4]); FMA2(acc[5], vB.y, wB.x, acc[5]);
                FMA2(acc[6], vB.x, wB.y, acc[6]); FMA2(acc[7], vB.y, wB.y, acc[7]);
            }

            #pragma unroll
            for (int k = 0; k < 4; k++) {
                ulonglong2 r;
                r.x = acc[2 * k];
                r.y = acc[2 * k + 1];
                *reinterpret_cast<ulonglong2*>(tp + (4 * g + k) * OYP) = r;
            }
        }
    }
    __syncwarp();      // warp-local: pass B reads only this warp's tmp region

    // ---- Pass B: out[c][bin] = sum_x Wx[x][ox_s] * tmp[cl][oy_s][x] ----
    if (cse == 1 || cse == 2) {
        // Broadcast fast path: flip table maps every px of row py to source
        // bin (py, 7-py) -> one reduction per (ch,py), row written 8x.
        const int cc = lane >> 3;             // channel within warp (0..3)
        const int py = lane & 7;
        const int oxs = 7 - py;

        unsigned long long a2 = 0ull;
        const float* wrow = s_WxT + oxs * WXP;
        const float* trow = s_tmp + (warp * 4 + cc) * CLP + py * OYP;

        for (int k = 0; k < ncx; k++) {
            const int x4 = xc0 + 4 * k;
            const ulonglong2 wv = *reinterpret_cast<const ulonglong2*>(wrow + x4);
            const ulonglong2 tv = *reinterpret_cast<const ulonglong2*>(trow + x4);
            FMA2(a2, tv.x, wv.x, a2);
            FMA2(a2, tv.y, wv.y, a2);
        }
        float lo, hi;
        UNPK2(lo, hi, a2);
        const float v = lo + hi;
        float4 q; q.x = v; q.y = v; q.z = v; q.w = v;

        float* __restrict__ ob =
            out + (size_t)n * (C_ * HOUT * WOUT)
                + (size_t)(h * 32 + warp * 4 + cc) * 64 + py * 8;
        *reinterpret_cast<float4*>(ob)     = q;
        *reinterpret_cast<float4*>(ob + 4) = q;
    } else {
        // General path (cse 0 or 3): per-bin reduction.
        #pragma unroll
        for (int half = 0; half < 2; half++) {
            const int bin = half * 32 + lane;
            const int py  = bin >> 3;
            const int px  = bin & 7;
            const int oy_s = (cse == 0) ? py : 7 - py;
            const int ox_s = px;

            unsigned long long a2[4];
            #pragma unroll
            for (int ch = 0; ch < 4; ch++) a2[ch] = 0ull;

            const float* wrow = s_WxT + ox_s * WXP;
            const float* trow = s_tmp + (warp * 4) * CLP + oy_s * OYP;

            for (int k = 0; k < ncx; k++) {
                const int x4 = xc0 + 4 * k;
                const ulonglong2 wv = *reinterpret_cast<const ulonglong2*>(wrow + x4);
                #pragma unroll
                for (int ch = 0; ch < 4; ch++) {
                    const ulonglong2 tv =
                        *reinterpret_cast<const ulonglong2*>(trow + ch * CLP + x4);
                    FMA2(a2[ch], tv.x, wv.x, a2[ch]);
                    FMA2(a2[ch], tv.y, wv.y, a2[ch]);
                }
            }

            float* __restrict__ ob =
                out + (size_t)n * (C_ * HOUT * WOUT)
                    + (size_t)(h * 32 + warp * 4) * 64 + bin;
            #pragma unroll
            for (int ch = 0; ch < 4; ch++) {
                float lo, hi;
                UNPK2(lo, hi, a2[ch]);
                ob[(size_t)ch * 64] = lo + hi;     // 128B coalesced per (half,ch)
            }
        }
    }
}

extern "C" void kernel_launch(void* const* d_in, const int* in_sizes, int n_in,
                              void* d_out, int out_size) {
    const float* feats      = (const float*)d_in[0];
    const int*   batch_idxs = (const int*)d_in[1];
    const int*   starts     = (const int*)d_in[2];
    const int*   goals      = (const int*)d_in[3];
    float*       out        = (float*)d_out;

    const int N = in_sizes[1];   // number of boxes (1024)

    prep_kernel<<<(N + 3) / 4, 256>>>(batch_idxs, starts, goals, N);

    // roi kernel launched with PDL so its blocks spin up while prep drains;
    // cudaGridDependencySynchronize() in-kernel guards the data dependency.
    cudaLaunchConfig_t cfg = {};
    cfg.gridDim  = dim3((unsigned)N, 2, 1);
    cfg.blockDim = dim3(256, 1, 1);
    cfg.dynamicSmemBytes = 0;
    cudaLaunchAttribute attr[1];
    attr[0].id = cudaLaunchAttributeProgrammaticStreamSerialization;
    attr[0].val.programmaticStreamSerializationAllowed = 1;
    cfg.attrs = attr;
    cfg.numAttrs = 1;
    cudaLaunchKernelEx(&cfg, roi_kernel, feats, out);
}